// round 3
// baseline (speedup 1.0000x reference)
#include <cuda_runtime.h>
#include <cstdint>

#define NN 50000
#define NE 800000
#define IND 512
#define HID 64
#define OUTD 40
#define TOT (NN * HID)

// ---------------- scratch (static device arrays; no allocation) -------------
__device__ float g_deg[NN];
__device__ float g_dis[NN];
__device__ float g_hs1[(size_t)NN * HID];   // d^-1/2[i] * (x@W1)[i]
__device__ float g_acc1[(size_t)NN * HID];  // self-loop + neighbor sum
__device__ float g_h[(size_t)NN * HID];     // post relu+dropout
__device__ float g_hs2[(size_t)NN * OUTD];
__device__ float g_acc2[(size_t)NN * OUTD];

// ---------------- degree / normalization ------------------------------------
__global__ void k_deg_init() {
    int i = blockIdx.x * blockDim.x + threadIdx.x;
    if (i < NN) g_deg[i] = 1.0f;  // self-loop
}

__global__ void k_deg_count(const int* __restrict__ dst) {
    int e = blockIdx.x * blockDim.x + threadIdx.x;
    if (e < NE) atomicAdd(&g_deg[dst[e]], 1.0f);
}

__global__ void k_dis() {
    int i = blockIdx.x * blockDim.x + threadIdx.x;
    if (i < NN) g_dis[i] = 1.0f / sqrtf(g_deg[i]);
}

// ---------------- GEMM1: hs1 = dis .* (x @ W1) ------------------------------
// block: 256 threads, computes 64 rows x 64 cols, BK=16
__global__ void k_gemm1(const float* __restrict__ x, const float* __restrict__ W1) {
    __shared__ float xs[64][17];
    __shared__ float ws[16][64];
    const int row0 = blockIdx.x * 64;
    const int t = threadIdx.x;
    const int tx = t & 15, ty = t >> 4;
    float acc[4][4] = {};

    for (int kb = 0; kb < IND; kb += 16) {
        {   // load x tile: 64 rows x 16 k, one float4 per thread
            int r = t >> 2, kk = (t & 3) << 2;
            int gr = row0 + r;
            float4 v = make_float4(0.f, 0.f, 0.f, 0.f);
            if (gr < NN)
                v = *(const float4*)(x + (size_t)gr * IND + kb + kk);
            xs[r][kk] = v.x; xs[r][kk + 1] = v.y; xs[r][kk + 2] = v.z; xs[r][kk + 3] = v.w;
        }
        {   // load W tile: 16 k x 64 cols
            int kk = t >> 4, c = (t & 15) << 2;
            float4 v = *(const float4*)(W1 + (size_t)(kb + kk) * HID + c);
            ws[kk][c] = v.x; ws[kk][c + 1] = v.y; ws[kk][c + 2] = v.z; ws[kk][c + 3] = v.w;
        }
        __syncthreads();
#pragma unroll
        for (int k = 0; k < 16; k++) {
            float a[4], b[4];
#pragma unroll
            for (int i = 0; i < 4; i++) a[i] = xs[ty * 4 + i][k];
#pragma unroll
            for (int j = 0; j < 4; j++) b[j] = ws[k][tx * 4 + j];
#pragma unroll
            for (int i = 0; i < 4; i++)
#pragma unroll
                for (int j = 0; j < 4; j++)
                    acc[i][j] = fmaf(a[i], b[j], acc[i][j]);
        }
        __syncthreads();
    }
#pragma unroll
    for (int i = 0; i < 4; i++) {
        int row = row0 + ty * 4 + i;
        if (row < NN) {
            float d = g_dis[row];
#pragma unroll
            for (int j = 0; j < 4; j++) {
                int c = tx * 4 + j;
                float v = d * acc[i][j];
                size_t idx = (size_t)row * HID + c;
                g_hs1[idx] = v;
                g_acc1[idx] = v;  // self-loop contribution
            }
        }
    }
}

// ---------------- scatter layer 1: acc1[dst] += hs1[src] --------------------
__global__ void k_scatter1(const int* __restrict__ src, const int* __restrict__ dst) {
    int gid = blockIdx.x * blockDim.x + threadIdx.x;  // NE*16 threads
    if (gid >= NE * 16) return;
    int e = gid >> 4;
    int c = (gid & 15) << 2;
    int s = src[e], d = dst[e];
    float4 v = *(const float4*)(g_hs1 + (size_t)s * HID + c);
    float* p = g_acc1 + (size_t)d * HID + c;
    atomicAdd(p + 0, v.x);
    atomicAdd(p + 1, v.y);
    atomicAdd(p + 2, v.z);
    atomicAdd(p + 3, v.w);
}

// ---------------- threefry2x32 (JAX-exact), keys (0, 42) --------------------
__device__ __forceinline__ uint32_t rotl32(uint32_t x, int r) {
    return (x << r) | (x >> (32 - r));
}

__device__ __forceinline__ void threefry_0_42(uint32_t x0, uint32_t x1,
                                              uint32_t& o0, uint32_t& o1) {
    const uint32_t k0 = 0u, k1 = 42u, k2 = 0x1BD11BDAu ^ 42u;
    x0 += k0; x1 += k1;
#define TF_ROUND(r) { x0 += x1; x1 = rotl32(x1, r); x1 ^= x0; }
    TF_ROUND(13) TF_ROUND(15) TF_ROUND(26) TF_ROUND(6)
    x0 += k1; x1 += k2 + 1u;
    TF_ROUND(17) TF_ROUND(29) TF_ROUND(16) TF_ROUND(24)
    x0 += k2; x1 += k0 + 2u;
    TF_ROUND(13) TF_ROUND(15) TF_ROUND(26) TF_ROUND(6)
    x0 += k0; x1 += k1 + 3u;
    TF_ROUND(17) TF_ROUND(29) TF_ROUND(16) TF_ROUND(24)
    x0 += k1; x1 += k2 + 4u;
    TF_ROUND(13) TF_ROUND(15) TF_ROUND(26) TF_ROUND(6)
    x0 += k2; x1 += k0 + 5u;
#undef TF_ROUND
    o0 = x0; o1 = x1;
}

// h = dropout(relu(dis*acc1 + b1))
// JAX threefry_partitionable (default since 0.4.36) 32-bit path:
//   bits[i] = o0 ^ o1 where (o0,o1) = threefry(key, (hi32(i), lo32(i))) = ((0,42),(0,i))
//   keep iff u < 0.5 iff bits < 0x80000000
__global__ void k_bias_relu_dropout(const float* __restrict__ b1) {
    int i = blockIdx.x * blockDim.x + threadIdx.x;
    if (i >= TOT) return;
    uint32_t o0, o1;
    threefry_0_42(0u, (uint32_t)i, o0, o1);
    uint32_t bits = o0 ^ o1;

    int row = i >> 6, c = i & 63;
    float v = fmaxf(g_dis[row] * g_acc1[i] + b1[c], 0.f);
    g_h[i] = (bits < 0x80000000u) ? v * 2.0f : 0.f;
}

// ---------------- GEMM2: hs2 = dis .* (h @ W2) ------------------------------
// block: 320 threads, 64 rows x 40 cols, K=64
__global__ void k_gemm2(const float* __restrict__ W2) {
    __shared__ float hsm[64][65];
    __shared__ float w2s[64][OUTD];
    const int row0 = blockIdx.x * 64;
    const int t = threadIdx.x;

    for (int idx = t; idx < 64 * 64; idx += 320) {
        int r = idx >> 6, k = idx & 63;
        int gr = row0 + r;
        hsm[r][k] = (gr < NN) ? g_h[(size_t)gr * HID + k] : 0.f;
    }
    for (int idx = t; idx < 64 * OUTD; idx += 320)
        w2s[idx / OUTD][idx % OUTD] = W2[idx];
    __syncthreads();

    int r8 = t / OUTD;      // 0..7
    int c = t % OUTD;
    float acc[8] = {};
#pragma unroll
    for (int k = 0; k < 64; k++) {
        float b = w2s[k][c];
#pragma unroll
        for (int i = 0; i < 8; i++)
            acc[i] = fmaf(hsm[r8 * 8 + i][k], b, acc[i]);
    }
#pragma unroll
    for (int i = 0; i < 8; i++) {
        int row = row0 + r8 * 8 + i;
        if (row < NN) {
            float v = g_dis[row] * acc[i];
            size_t idx = (size_t)row * OUTD + c;
            g_hs2[idx] = v;
            g_acc2[idx] = v;  // self-loop
        }
    }
}

// ---------------- scatter layer 2 -------------------------------------------
__global__ void k_scatter2(const int* __restrict__ src, const int* __restrict__ dst) {
    int gid = blockIdx.x * blockDim.x + threadIdx.x;  // NE*10 threads
    if (gid >= NE * 10) return;
    int e = gid / 10;
    int c = (gid % 10) << 2;
    int s = src[e], d = dst[e];
    float4 v = *(const float4*)(g_hs2 + (size_t)s * OUTD + c);
    float* p = g_acc2 + (size_t)d * OUTD + c;
    atomicAdd(p + 0, v.x);
    atomicAdd(p + 1, v.y);
    atomicAdd(p + 2, v.z);
    atomicAdd(p + 3, v.w);
}

// ---------------- bias + log_softmax ----------------------------------------
__global__ void k_logsoftmax(const float* __restrict__ b2, float* __restrict__ out) {
    int row = blockIdx.x * blockDim.y + threadIdx.y;
    if (row >= NN) return;
    int lane = threadIdx.x;
    float d = g_dis[row];
    int c1 = lane, c2 = lane + 32;
    float v1 = d * g_acc2[(size_t)row * OUTD + c1] + b2[c1];
    float v2 = -3.402823466e38f;
    if (c2 < OUTD) v2 = d * g_acc2[(size_t)row * OUTD + c2] + b2[c2];

    float m = fmaxf(v1, v2);
#pragma unroll
    for (int o = 16; o; o >>= 1) m = fmaxf(m, __shfl_xor_sync(0xFFFFFFFFu, m, o));
    float s = expf(v1 - m) + ((c2 < OUTD) ? expf(v2 - m) : 0.f);
#pragma unroll
    for (int o = 16; o; o >>= 1) s += __shfl_xor_sync(0xFFFFFFFFu, s, o);
    float lse = m + logf(s);

    out[(size_t)row * OUTD + c1] = v1 - lse;
    if (c2 < OUTD) out[(size_t)row * OUTD + c2] = v2 - lse;
}

// ---------------- launch -----------------------------------------------------
extern "C" void kernel_launch(void* const* d_in, const int* in_sizes, int n_in,
                              void* d_out, int out_size) {
    const float* x  = (const float*)d_in[0];
    const int*   ei = (const int*)d_in[1];     // [2, NE] row-major
    const float* W1 = (const float*)d_in[2];
    const float* b1 = (const float*)d_in[3];
    const float* W2 = (const float*)d_in[4];
    const float* b2 = (const float*)d_in[5];
    float* out = (float*)d_out;
    const int* src = ei;
    const int* dst = ei + NE;

    k_deg_init<<<(NN + 255) / 256, 256>>>();
    k_deg_count<<<(NE + 255) / 256, 256>>>(dst);
    k_dis<<<(NN + 255) / 256, 256>>>();

    k_gemm1<<<(NN + 63) / 64, 256>>>(x, W1);
    k_scatter1<<<(NE * 16 + 255) / 256, 256>>>(src, dst);
    k_bias_relu_dropout<<<(TOT + 255) / 256, 256>>>(b1);

    k_gemm2<<<(NN + 63) / 64, 320>>>(W2);
    k_scatter2<<<(NE * 10 + 255) / 256, 256>>>(src, dst);
    k_logsoftmax<<<(NN + 7) / 8, dim3(32, 8)>>>(b2, out);
}

// round 4
// speedup vs baseline: 1.4724x; 1.4724x over previous
#include <cuda_runtime.h>
#include <cstdint>
#include <math_constants.h>

#define NN 50000
#define NE 800000
#define IND 512
#define HID 64
#define OUTD 40

// ---------------- scratch (static device arrays; no allocation) -------------
__device__ float g_dis[NN];
__device__ int   g_cnt[NN];
__device__ int   g_cur[NN];
__device__ int   g_offs[NN + 1];
__device__ int   g_csr[NE];                 // src ids grouped by dst
__device__ float g_hs1[(size_t)NN * HID];   // d^-1/2[i] * (x@W1)[i]
__device__ float g_h[(size_t)NN * HID];     // post relu+dropout
__device__ float g_hs2[(size_t)NN * OUTD];  // d^-1/2[i] * (h@W2)[i]

// ---------------- CSR build --------------------------------------------------
__global__ void k_zero() {
    int i = blockIdx.x * blockDim.x + threadIdx.x;
    if (i < NN) { g_cnt[i] = 0; g_cur[i] = 0; }
}

__global__ void k_count(const int* __restrict__ dst) {
    int e = blockIdx.x * blockDim.x + threadIdx.x;
    if (e < NE) atomicAdd(&g_cnt[dst[e]], 1);
}

// single block, 1024 threads: exclusive scan of cnt -> offs; also dis = rsqrt(cnt+1)
__global__ void k_scan() {
    __shared__ int wsum[32];
    __shared__ int s_carry;
    int t = threadIdx.x, lane = t & 31, w = t >> 5;
    if (t == 0) s_carry = 0;
    __syncthreads();
    for (int base = 0; base < NN; base += 1024) {
        int i = base + t;
        int v = (i < NN) ? g_cnt[i] : 0;
        int x = v;
#pragma unroll
        for (int o = 1; o < 32; o <<= 1) {
            int n = __shfl_up_sync(0xFFFFFFFFu, x, o);
            if (lane >= o) x += n;
        }
        if (lane == 31) wsum[w] = x;
        __syncthreads();
        if (w == 0) {
            int y = wsum[lane];
#pragma unroll
            for (int o = 1; o < 32; o <<= 1) {
                int n = __shfl_up_sync(0xFFFFFFFFu, y, o);
                if (lane >= o) y += n;
            }
            wsum[lane] = y;
        }
        __syncthreads();
        int incl = x + (w ? wsum[w - 1] : 0);
        int carry = s_carry;
        if (i < NN) {
            g_offs[i] = carry + incl - v;
            g_dis[i] = rsqrtf((float)(v + 1));   // +1 self-loop
        }
        __syncthreads();
        if (t == 1023) s_carry = carry + incl;
        __syncthreads();
    }
    if (t == 0) g_offs[NN] = s_carry;
}

__global__ void k_fill(const int* __restrict__ src, const int* __restrict__ dst) {
    int e = blockIdx.x * blockDim.x + threadIdx.x;
    if (e >= NE) return;
    int d = dst[e];
    int pos = g_offs[d] + atomicAdd(&g_cur[d], 1);
    g_csr[pos] = src[e];
}

// ---------------- GEMM1: hs1 = dis .* (x @ W1) ------------------------------
// 128 threads, tile 128 rows x 64 cols, microtile 8x8, BK=16
__global__ __launch_bounds__(128) void k_gemm1(const float* __restrict__ x,
                                               const float* __restrict__ W1) {
    __shared__ float xs[128][17];
    __shared__ float ws[16][64];
    const int row0 = blockIdx.x * 128;
    const int t = threadIdx.x;
    const int tx = t & 7;    // col group (8 cols)
    const int ty = t >> 3;   // row group (8 rows)
    float acc[8][8] = {};

    for (int kb = 0; kb < IND; kb += 16) {
        // x tile: 128 rows x 16 k = 512 float4, 4 per thread (64B chunks/lane-group)
#pragma unroll
        for (int i = 0; i < 4; i++) {
            int f = t + 128 * i;
            int r = f >> 2, kq = (f & 3) << 2;
            int gr = row0 + r;
            float4 v = make_float4(0.f, 0.f, 0.f, 0.f);
            if (gr < NN) v = *(const float4*)(x + (size_t)gr * IND + kb + kq);
            xs[r][kq] = v.x; xs[r][kq + 1] = v.y; xs[r][kq + 2] = v.z; xs[r][kq + 3] = v.w;
        }
        // W tile: 16 k x 64 cols = 256 float4, 2 per thread
#pragma unroll
        for (int i = 0; i < 2; i++) {
            int f = t + 128 * i;
            int kk = f >> 4, c4 = (f & 15) << 2;
            float4 v = *(const float4*)(W1 + (size_t)(kb + kk) * HID + c4);
            ws[kk][c4] = v.x; ws[kk][c4 + 1] = v.y; ws[kk][c4 + 2] = v.z; ws[kk][c4 + 3] = v.w;
        }
        __syncthreads();
#pragma unroll
        for (int k = 0; k < 16; k++) {
            float a[8], b[8];
#pragma unroll
            for (int i = 0; i < 8; i++) a[i] = xs[ty * 8 + i][k];
#pragma unroll
            for (int j = 0; j < 8; j++) b[j] = ws[k][tx * 8 + j];
#pragma unroll
            for (int i = 0; i < 8; i++)
#pragma unroll
                for (int j = 0; j < 8; j++)
                    acc[i][j] = fmaf(a[i], b[j], acc[i][j]);
        }
        __syncthreads();
    }
#pragma unroll
    for (int i = 0; i < 8; i++) {
        int row = row0 + ty * 8 + i;
        if (row < NN) {
            float d = g_dis[row];
            float4 o0 = make_float4(d * acc[i][0], d * acc[i][1], d * acc[i][2], d * acc[i][3]);
            float4 o1 = make_float4(d * acc[i][4], d * acc[i][5], d * acc[i][6], d * acc[i][7]);
            float* p = g_hs1 + (size_t)row * HID + tx * 8;
            *(float4*)p = o0;
            *(float4*)(p + 4) = o1;
        }
    }
}

// ---------------- threefry2x32 (JAX partitionable), key (0, 42) -------------
__device__ __forceinline__ uint32_t rotl32(uint32_t x, int r) {
    return (x << r) | (x >> (32 - r));
}

__device__ __forceinline__ uint32_t tf_bits(uint32_t i) {
    // counts (hi,lo) = (0, i); output fold o0 ^ o1
    uint32_t x0 = 0u, x1 = i;
    const uint32_t k0 = 0u, k1 = 42u, k2 = 0x1BD11BDAu ^ 42u;
    x0 += k0; x1 += k1;
#define TF_ROUND(r) { x0 += x1; x1 = rotl32(x1, r); x1 ^= x0; }
    TF_ROUND(13) TF_ROUND(15) TF_ROUND(26) TF_ROUND(6)
    x0 += k1; x1 += k2 + 1u;
    TF_ROUND(17) TF_ROUND(29) TF_ROUND(16) TF_ROUND(24)
    x0 += k2; x1 += k0 + 2u;
    TF_ROUND(13) TF_ROUND(15) TF_ROUND(26) TF_ROUND(6)
    x0 += k0; x1 += k1 + 3u;
    TF_ROUND(17) TF_ROUND(29) TF_ROUND(16) TF_ROUND(24)
    x0 += k1; x1 += k2 + 4u;
    TF_ROUND(13) TF_ROUND(15) TF_ROUND(26) TF_ROUND(6)
    x0 += k2; x1 += k0 + 5u;
#undef TF_ROUND
    return x0 ^ x1;
}

// ---------------- agg1: warp/node gather + bias + relu + dropout ------------
__global__ void k_agg1(const float* __restrict__ b1) {
    int node = blockIdx.x * (blockDim.x >> 5) + (threadIdx.x >> 5);
    if (node >= NN) return;
    int lane = threadIdx.x & 31;

    const float* base = g_hs1 + (size_t)node * HID;
    float a0 = base[lane];          // self-loop contribution
    float a1 = base[lane + 32];

    int beg = g_offs[node], end = g_offs[node + 1];
    for (int k0 = beg; k0 < end; k0 += 32) {
        int myk = k0 + lane;
        int sv = (myk < end) ? g_csr[myk] : 0;
        int m = min(32, end - k0);
        for (int j = 0; j < m; j++) {
            int s = __shfl_sync(0xFFFFFFFFu, sv, j);
            const float* p = g_hs1 + (size_t)s * HID;
            a0 += p[lane];
            a1 += p[lane + 32];
        }
    }
    float d = g_dis[node];
    float v0 = fmaxf(fmaf(d, a0, b1[lane]), 0.f);
    float v1 = fmaxf(fmaf(d, a1, b1[lane + 32]), 0.f);
    uint32_t i0 = (uint32_t)node * HID + lane;
    g_h[i0]      = (tf_bits(i0)      < 0x80000000u) ? v0 * 2.0f : 0.f;
    g_h[i0 + 32] = (tf_bits(i0 + 32) < 0x80000000u) ? v1 * 2.0f : 0.f;
}

// ---------------- GEMM2: hs2 = dis .* (h @ W2) ------------------------------
__global__ void k_gemm2(const float* __restrict__ W2) {
    __shared__ float hsm[64][65];
    __shared__ float w2s[64][OUTD];
    const int row0 = blockIdx.x * 64;
    const int t = threadIdx.x;

    for (int idx = t; idx < 64 * 64; idx += 320) {
        int r = idx >> 6, k = idx & 63;
        int gr = row0 + r;
        hsm[r][k] = (gr < NN) ? g_h[(size_t)gr * HID + k] : 0.f;
    }
    for (int idx = t; idx < 64 * OUTD; idx += 320)
        w2s[idx / OUTD][idx % OUTD] = W2[idx];
    __syncthreads();

    int r8 = t / OUTD;
    int c = t % OUTD;
    float acc[8] = {};
#pragma unroll
    for (int k = 0; k < 64; k++) {
        float b = w2s[k][c];
#pragma unroll
        for (int i = 0; i < 8; i++)
            acc[i] = fmaf(hsm[r8 * 8 + i][k], b, acc[i]);
    }
#pragma unroll
    for (int i = 0; i < 8; i++) {
        int row = row0 + r8 * 8 + i;
        if (row < NN)
            g_hs2[(size_t)row * OUTD + c] = g_dis[row] * acc[i];
    }
}

// ---------------- agg2: warp/node gather + bias + log_softmax ---------------
__global__ void k_agg2(const float* __restrict__ b2, float* __restrict__ out) {
    int node = blockIdx.x * (blockDim.x >> 5) + (threadIdx.x >> 5);
    if (node >= NN) return;
    int lane = threadIdx.x & 31;

    const float* base = g_hs2 + (size_t)node * OUTD;
    float a0 = base[lane];                               // cols 0..31
    float a1 = (lane < 8) ? base[lane + 32] : 0.f;       // cols 32..39

    int beg = g_offs[node], end = g_offs[node + 1];
    for (int k0 = beg; k0 < end; k0 += 32) {
        int myk = k0 + lane;
        int sv = (myk < end) ? g_csr[myk] : 0;
        int m = min(32, end - k0);
        for (int j = 0; j < m; j++) {
            int s = __shfl_sync(0xFFFFFFFFu, sv, j);
            const float* p = g_hs2 + (size_t)s * OUTD;
            a0 += p[lane];
            if (lane < 8) a1 += p[lane + 32];
        }
    }
    float d = g_dis[node];
    float v0 = fmaf(d, a0, b2[lane]);
    float v1 = (lane < 8) ? fmaf(d, a1, b2[lane + 32]) : -CUDART_INF_F;

    float m = fmaxf(v0, v1);
#pragma unroll
    for (int o = 16; o; o >>= 1) m = fmaxf(m, __shfl_xor_sync(0xFFFFFFFFu, m, o));
    float s = expf(v0 - m) + ((lane < 8) ? expf(v1 - m) : 0.f);
#pragma unroll
    for (int o = 16; o; o >>= 1) s += __shfl_xor_sync(0xFFFFFFFFu, s, o);
    float lse = m + logf(s);

    float* op = out + (size_t)node * OUTD;
    op[lane] = v0 - lse;
    if (lane < 8) op[lane + 32] = v1 - lse;
}

// ---------------- launch -----------------------------------------------------
extern "C" void kernel_launch(void* const* d_in, const int* in_sizes, int n_in,
                              void* d_out, int out_size) {
    const float* x  = (const float*)d_in[0];
    const int*   ei = (const int*)d_in[1];     // [2, NE] row-major
    const float* W1 = (const float*)d_in[2];
    const float* b1 = (const float*)d_in[3];
    const float* W2 = (const float*)d_in[4];
    const float* b2 = (const float*)d_in[5];
    float* out = (float*)d_out;
    const int* src = ei;
    const int* dst = ei + NE;

    k_zero<<<(NN + 255) / 256, 256>>>();
    k_count<<<(NE + 255) / 256, 256>>>(dst);
    k_scan<<<1, 1024>>>();
    k_fill<<<(NE + 255) / 256, 256>>>(src, dst);

    k_gemm1<<<(NN + 127) / 128, 128>>>(x, W1);
    k_agg1<<<(NN * 32 + 255) / 256, 256>>>(b1);

    k_gemm2<<<(NN + 63) / 64, 320>>>(W2);
    k_agg2<<<(NN * 32 + 255) / 256, 256>>>(b2, out);
}

// round 5
// speedup vs baseline: 1.6390x; 1.1131x over previous
#include <cuda_runtime.h>
#include <cstdint>
#include <math_constants.h>

#define NN 50000
#define NE 800000
#define IND 512
#define HID 64
#define OUTD 40

// ---------------- scratch (static device arrays; no allocation) -------------
__device__ float g_dis[NN];
__device__ int   g_cnt[NN];
__device__ int   g_cur[NN];
__device__ int   g_offs[NN + 1];
__device__ int   g_csr[NE];                 // src ids grouped by dst
__device__ float g_hs1[(size_t)NN * HID];   // d^-1/2[i] * (x@W1)[i]
__device__ float g_h[(size_t)NN * HID];     // post relu+dropout
__device__ float g_hs2[(size_t)NN * OUTD];  // d^-1/2[i] * (h@W2)[i]

// ---------------- CSR build --------------------------------------------------
__global__ void k_zero() {
    int i = blockIdx.x * blockDim.x + threadIdx.x;
    if (i < NN) g_cnt[i] = 0;
}

__global__ void k_count(const int* __restrict__ dst) {
    int i = (blockIdx.x * blockDim.x + threadIdx.x) * 4;
    if (i >= NE) return;
    int4 d = *(const int4*)(dst + i);
    atomicAdd(&g_cnt[d.x], 1);
    atomicAdd(&g_cnt[d.y], 1);
    atomicAdd(&g_cnt[d.z], 1);
    atomicAdd(&g_cnt[d.w], 1);
}

// single block, 1024 threads, 4 items/thread: exclusive scan cnt -> offs,cur; dis
__global__ void k_scan() {
    __shared__ int wsum[32];
    __shared__ int s_carry;
    int t = threadIdx.x, lane = t & 31, w = t >> 5;
    if (t == 0) s_carry = 0;
    __syncthreads();
    for (int base = 0; base < NN; base += 4096) {
        int i0 = base + t * 4;
        int v[4];
#pragma unroll
        for (int m = 0; m < 4; m++) v[m] = (i0 + m < NN) ? g_cnt[i0 + m] : 0;
        int s = v[0] + v[1] + v[2] + v[3];
        int x = s;
#pragma unroll
        for (int o = 1; o < 32; o <<= 1) {
            int n = __shfl_up_sync(0xFFFFFFFFu, x, o);
            if (lane >= o) x += n;
        }
        if (lane == 31) wsum[w] = x;
        __syncthreads();
        if (w == 0) {
            int y = wsum[lane];
#pragma unroll
            for (int o = 1; o < 32; o <<= 1) {
                int n = __shfl_up_sync(0xFFFFFFFFu, y, o);
                if (lane >= o) y += n;
            }
            wsum[lane] = y;
        }
        __syncthreads();
        int carry = s_carry;
        int run = carry + x - s + (w ? wsum[w - 1] : 0);
#pragma unroll
        for (int m = 0; m < 4; m++) {
            int i = i0 + m;
            if (i < NN) {
                g_offs[i] = run;
                g_cur[i]  = run;
                g_dis[i]  = rsqrtf((float)(v[m] + 1));   // +1 self-loop
                run += v[m];
            }
        }
        __syncthreads();
        if (t == 0) s_carry = carry + wsum[31];
        __syncthreads();
    }
    if (t == 0) g_offs[NN] = s_carry;
}

__global__ void k_fill(const int* __restrict__ src, const int* __restrict__ dst) {
    int i = (blockIdx.x * blockDim.x + threadIdx.x) * 4;
    if (i >= NE) return;
    int4 s4 = *(const int4*)(src + i);
    int4 d4 = *(const int4*)(dst + i);
    g_csr[atomicAdd(&g_cur[d4.x], 1)] = s4.x;
    g_csr[atomicAdd(&g_cur[d4.y], 1)] = s4.y;
    g_csr[atomicAdd(&g_cur[d4.z], 1)] = s4.z;
    g_csr[atomicAdd(&g_cur[d4.w], 1)] = s4.w;
}

// ---------------- GEMM1 (TF32 tensor cores): hs1 = dis .* (x @ W1) ----------
// 256 threads = 8 warps (4M x 2N), block tile 128x64, warp tile 32x32, BK=32
__device__ __forceinline__ uint32_t f2tf32(float f) {
    uint32_t r;
    asm("cvt.rna.tf32.f32 %0, %1;" : "=r"(r) : "f"(f));
    return r;
}

__device__ __forceinline__ void mma_tf32(float* c, const uint32_t* a, const uint32_t* b) {
    asm volatile(
        "mma.sync.aligned.m16n8k8.row.col.f32.tf32.tf32.f32 "
        "{%0,%1,%2,%3}, {%4,%5,%6,%7}, {%8,%9}, {%0,%1,%2,%3};"
        : "+f"(c[0]), "+f"(c[1]), "+f"(c[2]), "+f"(c[3])
        : "r"(a[0]), "r"(a[1]), "r"(a[2]), "r"(a[3]), "r"(b[0]), "r"(b[1]));
}

#define XPAD 36
#define WPAD 72

__global__ __launch_bounds__(256) void k_gemm1(const float* __restrict__ x,
                                               const float* __restrict__ W1) {
    __shared__ uint32_t xs[128][XPAD];
    __shared__ uint32_t ws[32][WPAD];
    const int row0 = blockIdx.x * 128;
    const int t = threadIdx.x;
    const int wid = t >> 5, lane = t & 31;
    const int wm = wid >> 1, wn = wid & 1;       // warp grid 4x2
    const int g = lane >> 2, tig = lane & 3;     // mma fragment coords

    float acc[2][4][4] = {};                      // [Mtile][Ntile][4]

    for (int kb = 0; kb < IND; kb += 32) {
        // x tile: 128 rows x 32 k = 1024 float4; 4 per thread
#pragma unroll
        for (int i = 0; i < 4; i++) {
            int f = t + 256 * i;
            int r = f >> 3, q = (f & 7) << 2;
            int gr = row0 + r;
            float4 v = make_float4(0.f, 0.f, 0.f, 0.f);
            if (gr < NN) v = *(const float4*)(x + (size_t)gr * IND + kb + q);
            xs[r][q]     = f2tf32(v.x);
            xs[r][q + 1] = f2tf32(v.y);
            xs[r][q + 2] = f2tf32(v.z);
            xs[r][q + 3] = f2tf32(v.w);
        }
        // W tile: 32 k x 64 cols = 512 float4; 2 per thread
#pragma unroll
        for (int i = 0; i < 2; i++) {
            int f = t + 256 * i;
            int kk = f >> 4, c4 = (f & 15) << 2;
            float4 v = *(const float4*)(W1 + (size_t)(kb + kk) * HID + c4);
            ws[kk][c4]     = f2tf32(v.x);
            ws[kk][c4 + 1] = f2tf32(v.y);
            ws[kk][c4 + 2] = f2tf32(v.z);
            ws[kk][c4 + 3] = f2tf32(v.w);
        }
        __syncthreads();
#pragma unroll
        for (int k8 = 0; k8 < 4; k8++) {
            int k0 = k8 * 8;
            uint32_t a[2][4], b[4][2];
#pragma unroll
            for (int i = 0; i < 2; i++) {
                int rb = wm * 32 + i * 16;
                a[i][0] = xs[rb + g][k0 + tig];
                a[i][1] = xs[rb + g + 8][k0 + tig];
                a[i][2] = xs[rb + g][k0 + tig + 4];
                a[i][3] = xs[rb + g + 8][k0 + tig + 4];
            }
#pragma unroll
            for (int j = 0; j < 4; j++) {
                int nb = wn * 32 + j * 8 + g;
                b[j][0] = ws[k0 + tig][nb];
                b[j][1] = ws[k0 + tig + 4][nb];
            }
#pragma unroll
            for (int i = 0; i < 2; i++)
#pragma unroll
                for (int j = 0; j < 4; j++)
                    mma_tf32(acc[i][j], a[i], b[j]);
        }
        __syncthreads();
    }

    // epilogue: scale by dis, store float2 per (tile,row)
#pragma unroll
    for (int i = 0; i < 2; i++) {
        int r_lo = row0 + wm * 32 + i * 16 + g;
        int r_hi = r_lo + 8;
        float d_lo = (r_lo < NN) ? g_dis[r_lo] : 0.f;
        float d_hi = (r_hi < NN) ? g_dis[r_hi] : 0.f;
#pragma unroll
        for (int j = 0; j < 4; j++) {
            int c = wn * 32 + j * 8 + 2 * tig;
            if (r_lo < NN)
                *(float2*)(g_hs1 + (size_t)r_lo * HID + c) =
                    make_float2(d_lo * acc[i][j][0], d_lo * acc[i][j][1]);
            if (r_hi < NN)
                *(float2*)(g_hs1 + (size_t)r_hi * HID + c) =
                    make_float2(d_hi * acc[i][j][2], d_hi * acc[i][j][3]);
        }
    }
}

// ---------------- threefry2x32 (JAX partitionable), key (0, 42) -------------
__device__ __forceinline__ uint32_t rotl32(uint32_t x, int r) {
    return (x << r) | (x >> (32 - r));
}

__device__ __forceinline__ uint32_t tf_bits(uint32_t i) {
    uint32_t x0 = 0u, x1 = i;
    const uint32_t k0 = 0u, k1 = 42u, k2 = 0x1BD11BDAu ^ 42u;
    x0 += k0; x1 += k1;
#define TF_ROUND(r) { x0 += x1; x1 = rotl32(x1, r); x1 ^= x0; }
    TF_ROUND(13) TF_ROUND(15) TF_ROUND(26) TF_ROUND(6)
    x0 += k1; x1 += k2 + 1u;
    TF_ROUND(17) TF_ROUND(29) TF_ROUND(16) TF_ROUND(24)
    x0 += k2; x1 += k0 + 2u;
    TF_ROUND(13) TF_ROUND(15) TF_ROUND(26) TF_ROUND(6)
    x0 += k0; x1 += k1 + 3u;
    TF_ROUND(17) TF_ROUND(29) TF_ROUND(16) TF_ROUND(24)
    x0 += k1; x1 += k2 + 4u;
    TF_ROUND(13) TF_ROUND(15) TF_ROUND(26) TF_ROUND(6)
    x0 += k2; x1 += k0 + 5u;
#undef TF_ROUND
    return x0 ^ x1;
}

// ---------------- agg1: warp/node gather + bias + relu + dropout ------------
__global__ void k_agg1(const float* __restrict__ b1) {
    int node = blockIdx.x * (blockDim.x >> 5) + (threadIdx.x >> 5);
    if (node >= NN) return;
    int lane = threadIdx.x & 31;

    const float* base = g_hs1 + (size_t)node * HID;
    float a0 = base[lane];          // self-loop contribution
    float a1 = base[lane + 32];

    int beg = g_offs[node], end = g_offs[node + 1];
    for (int k0 = beg; k0 < end; k0 += 32) {
        int myk = k0 + lane;
        int sv = (myk < end) ? g_csr[myk] : 0;
        int m = min(32, end - k0);
        for (int j = 0; j < m; j++) {
            int s = __shfl_sync(0xFFFFFFFFu, sv, j);
            const float* p = g_hs1 + (size_t)s * HID;
            a0 += p[lane];
            a1 += p[lane + 32];
        }
    }
    float d = g_dis[node];
    float v0 = fmaxf(fmaf(d, a0, b1[lane]), 0.f);
    float v1 = fmaxf(fmaf(d, a1, b1[lane + 32]), 0.f);
    uint32_t i0 = (uint32_t)node * HID + lane;
    g_h[i0]      = (tf_bits(i0)      < 0x80000000u) ? v0 * 2.0f : 0.f;
    g_h[i0 + 32] = (tf_bits(i0 + 32) < 0x80000000u) ? v1 * 2.0f : 0.f;
}

// ---------------- GEMM2: hs2 = dis .* (h @ W2) ------------------------------
__global__ void k_gemm2(const float* __restrict__ W2) {
    __shared__ float hsm[64][65];
    __shared__ float w2s[64][OUTD];
    const int row0 = blockIdx.x * 64;
    const int t = threadIdx.x;

    for (int idx = t; idx < 64 * 64; idx += 320) {
        int r = idx >> 6, k = idx & 63;
        int gr = row0 + r;
        hsm[r][k] = (gr < NN) ? g_h[(size_t)gr * HID + k] : 0.f;
    }
    for (int idx = t; idx < 64 * OUTD; idx += 320)
        w2s[idx / OUTD][idx % OUTD] = W2[idx];
    __syncthreads();

    int r8 = t / OUTD;
    int c = t % OUTD;
    float acc[8] = {};
#pragma unroll
    for (int k = 0; k < 64; k++) {
        float b = w2s[k][c];
#pragma unroll
        for (int i = 0; i < 8; i++)
            acc[i] = fmaf(hsm[r8 * 8 + i][k], b, acc[i]);
    }
#pragma unroll
    for (int i = 0; i < 8; i++) {
        int row = row0 + r8 * 8 + i;
        if (row < NN)
            g_hs2[(size_t)row * OUTD + c] = g_dis[row] * acc[i];
    }
}

// ---------------- agg2: warp/node gather + bias + log_softmax ---------------
__global__ void k_agg2(const float* __restrict__ b2, float* __restrict__ out) {
    int node = blockIdx.x * (blockDim.x >> 5) + (threadIdx.x >> 5);
    if (node >= NN) return;
    int lane = threadIdx.x & 31;

    const float* base = g_hs2 + (size_t)node * OUTD;
    float a0 = base[lane];                               // cols 0..31
    float a1 = (lane < 8) ? base[lane + 32] : 0.f;       // cols 32..39

    int beg = g_offs[node], end = g_offs[node + 1];
    for (int k0 = beg; k0 < end; k0 += 32) {
        int myk = k0 + lane;
        int sv = (myk < end) ? g_csr[myk] : 0;
        int m = min(32, end - k0);
        for (int j = 0; j < m; j++) {
            int s = __shfl_sync(0xFFFFFFFFu, sv, j);
            const float* p = g_hs2 + (size_t)s * OUTD;
            a0 += p[lane];
            if (lane < 8) a1 += p[lane + 32];
        }
    }
    float d = g_dis[node];
    float v0 = fmaf(d, a0, b2[lane]);
    float v1 = (lane < 8) ? fmaf(d, a1, b2[lane + 32]) : -CUDART_INF_F;

    float m = fmaxf(v0, v1);
#pragma unroll
    for (int o = 16; o; o >>= 1) m = fmaxf(m, __shfl_xor_sync(0xFFFFFFFFu, m, o));
    float s = expf(v0 - m) + ((lane < 8) ? expf(v1 - m) : 0.f);
#pragma unroll
    for (int o = 16; o; o >>= 1) s += __shfl_xor_sync(0xFFFFFFFFu, s, o);
    float lse = m + logf(s);

    float* op = out + (size_t)node * OUTD;
    op[lane] = v0 - lse;
    if (lane < 8) op[lane + 32] = v1 - lse;
}

// ---------------- launch -----------------------------------------------------
extern "C" void kernel_launch(void* const* d_in, const int* in_sizes, int n_in,
                              void* d_out, int out_size) {
    const float* x  = (const float*)d_in[0];
    const int*   ei = (const int*)d_in[1];     // [2, NE] row-major
    const float* W1 = (const float*)d_in[2];
    const float* b1 = (const float*)d_in[3];
    const float* W2 = (const float*)d_in[4];
    const float* b2 = (const float*)d_in[5];
    float* out = (float*)d_out;
    const int* src = ei;
    const int* dst = ei + NE;

    k_zero<<<(NN + 255) / 256, 256>>>();
    k_count<<<(NE / 4 + 255) / 256, 256>>>(dst);
    k_scan<<<1, 1024>>>();
    k_fill<<<(NE / 4 + 255) / 256, 256>>>(src, dst);

    k_gemm1<<<(NN + 127) / 128, 256>>>(x, W1);
    k_agg1<<<(NN * 32 + 255) / 256, 256>>>(b1);

    k_gemm2<<<(NN + 63) / 64, 320>>>(W2);
    k_agg2<<<(NN * 32 + 255) / 256, 256>>>(b2, out);
}

// round 7
// speedup vs baseline: 2.0339x; 1.2409x over previous
#include <cuda_runtime.h>
#include <cstdint>
#include <math_constants.h>

#define NN 50000
#define NE 800000
#define IND 512
#define HID 64
#define OUTD 40

// ---------------- scratch (static device arrays; no allocation) -------------
__device__ float g_dis[NN];
__device__ int   g_cnt[NN];
__device__ int   g_cur[NN];
__device__ int   g_offs[NN + 1];
__device__ int   g_bsum[64];
__device__ int   g_bbase[64];
__device__ int   g_csr[NE];                 // src ids grouped by dst
__device__ float g_hs1[(size_t)NN * HID];   // d^-1/2[i] * (x@W1)[i]
__device__ float g_h[(size_t)NN * HID];     // post relu+dropout
__device__ float g_hs2[(size_t)NN * OUTD];  // d^-1/2[i] * (h@W2)[i]

// ---------------- CSR build --------------------------------------------------
__global__ void k_zero() {
    int i = blockIdx.x * blockDim.x + threadIdx.x;
    if (i < NN) g_cnt[i] = 0;
}

__global__ void k_count(const int* __restrict__ dst) {
    int i = (blockIdx.x * blockDim.x + threadIdx.x) * 4;
    if (i >= NE) return;
    int4 d = *(const int4*)(dst + i);
    atomicAdd(&g_cnt[d.x], 1);
    atomicAdd(&g_cnt[d.y], 1);
    atomicAdd(&g_cnt[d.z], 1);
    atomicAdd(&g_cnt[d.w], 1);
}

// scan1: per-block (1024 nodes) sums
__global__ void k_scan1() {
    int t = threadIdx.x, lane = t & 31, w = t >> 5;
    int i = blockIdx.x * 1024 + t;
    int v = (i < NN) ? g_cnt[i] : 0;
#pragma unroll
    for (int o = 16; o; o >>= 1) v += __shfl_xor_sync(0xFFFFFFFFu, v, o);
    __shared__ int ws[32];
    if (lane == 0) ws[w] = v;
    __syncthreads();
    if (w == 0) {
        int y = ws[lane];
#pragma unroll
        for (int o = 16; o; o >>= 1) y += __shfl_xor_sync(0xFFFFFFFFu, y, o);
        if (lane == 0) g_bsum[blockIdx.x] = y;
    }
}

// scan2: single block, exclusive scan of 49 block sums
__global__ void k_scan2() {
    __shared__ int sm[64];
    int t = threadIdx.x;
    int v0 = (t < 49) ? g_bsum[t] : 0;
    sm[t] = v0;
    __syncthreads();
    for (int o = 1; o < 64; o <<= 1) {
        int v = (t >= o) ? sm[t - o] : 0;
        __syncthreads();
        sm[t] += v;
        __syncthreads();
    }
    if (t < 49) g_bbase[t] = sm[t] - v0;
}

// scan3: per-block exclusive scan + base -> offs, cur, dis
__global__ void k_scan3() {
    __shared__ int wsum[32];
    int t = threadIdx.x, lane = t & 31, w = t >> 5;
    int i = blockIdx.x * 1024 + t;
    int v = (i < NN) ? g_cnt[i] : 0;
    int x = v;
#pragma unroll
    for (int o = 1; o < 32; o <<= 1) {
        int n = __shfl_up_sync(0xFFFFFFFFu, x, o);
        if (lane >= o) x += n;
    }
    if (lane == 31) wsum[w] = x;
    __syncthreads();
    if (w == 0) {
        int y = wsum[lane];
#pragma unroll
        for (int o = 1; o < 32; o <<= 1) {
            int n = __shfl_up_sync(0xFFFFFFFFu, y, o);
            if (lane >= o) y += n;
        }
        wsum[lane] = y;
    }
    __syncthreads();
    int excl = g_bbase[blockIdx.x] + x - v + (w ? wsum[w - 1] : 0);
    if (i < NN) {
        g_offs[i] = excl;
        g_cur[i]  = excl;
        g_dis[i]  = rsqrtf((float)(v + 1));   // +1 self-loop
    }
    if (i == 0) g_offs[NN] = NE;
}

__global__ void k_fill(const int* __restrict__ src, const int* __restrict__ dst) {
    int i = (blockIdx.x * blockDim.x + threadIdx.x) * 4;
    if (i >= NE) return;
    int4 s4 = *(const int4*)(src + i);
    int4 d4 = *(const int4*)(dst + i);
    g_csr[atomicAdd(&g_cur[d4.x], 1)] = s4.x;
    g_csr[atomicAdd(&g_cur[d4.y], 1)] = s4.y;
    g_csr[atomicAdd(&g_cur[d4.z], 1)] = s4.z;
    g_csr[atomicAdd(&g_cur[d4.w], 1)] = s4.w;
}

// ---------------- GEMM1 (TF32 tensor cores): hs1 = dis .* (x @ W1) ----------
__device__ __forceinline__ uint32_t f2tf32(float f) {
    uint32_t r;
    asm("cvt.rna.tf32.f32 %0, %1;" : "=r"(r) : "f"(f));
    return r;
}

__device__ __forceinline__ void mma_tf32(float* c, const uint32_t* a, const uint32_t* b) {
    asm volatile(
        "mma.sync.aligned.m16n8k8.row.col.f32.tf32.tf32.f32 "
        "{%0,%1,%2,%3}, {%4,%5,%6,%7}, {%8,%9}, {%0,%1,%2,%3};"
        : "+f"(c[0]), "+f"(c[1]), "+f"(c[2]), "+f"(c[3])
        : "r"(a[0]), "r"(a[1]), "r"(a[2]), "r"(a[3]), "r"(b[0]), "r"(b[1]));
}

#define XPAD 36
#define WPAD 72

__global__ __launch_bounds__(256) void k_gemm1(const float* __restrict__ x,
                                               const float* __restrict__ W1) {
    __shared__ uint32_t xs[128][XPAD];
    __shared__ uint32_t ws[32][WPAD];
    const int row0 = blockIdx.x * 128;
    const int t = threadIdx.x;
    const int wid = t >> 5, lane = t & 31;
    const int wm = wid >> 1, wn = wid & 1;
    const int g = lane >> 2, tig = lane & 3;

    float acc[2][4][4] = {};

    for (int kb = 0; kb < IND; kb += 32) {
#pragma unroll
        for (int i = 0; i < 4; i++) {
            int f = t + 256 * i;
            int r = f >> 3, q = (f & 7) << 2;
            int gr = row0 + r;
            float4 v = make_float4(0.f, 0.f, 0.f, 0.f);
            if (gr < NN) v = *(const float4*)(x + (size_t)gr * IND + kb + q);
            xs[r][q]     = f2tf32(v.x);
            xs[r][q + 1] = f2tf32(v.y);
            xs[r][q + 2] = f2tf32(v.z);
            xs[r][q + 3] = f2tf32(v.w);
        }
#pragma unroll
        for (int i = 0; i < 2; i++) {
            int f = t + 256 * i;
            int kk = f >> 4, c4 = (f & 15) << 2;
            float4 v = *(const float4*)(W1 + (size_t)(kb + kk) * HID + c4);
            ws[kk][c4]     = f2tf32(v.x);
            ws[kk][c4 + 1] = f2tf32(v.y);
            ws[kk][c4 + 2] = f2tf32(v.z);
            ws[kk][c4 + 3] = f2tf32(v.w);
        }
        __syncthreads();
#pragma unroll
        for (int k8 = 0; k8 < 4; k8++) {
            int k0 = k8 * 8;
            uint32_t a[2][4], b[4][2];
#pragma unroll
            for (int i = 0; i < 2; i++) {
                int rb = wm * 32 + i * 16;
                a[i][0] = xs[rb + g][k0 + tig];
                a[i][1] = xs[rb + g + 8][k0 + tig];
                a[i][2] = xs[rb + g][k0 + tig + 4];
                a[i][3] = xs[rb + g + 8][k0 + tig + 4];
            }
#pragma unroll
            for (int j = 0; j < 4; j++) {
                int nb = wn * 32 + j * 8 + g;
                b[j][0] = ws[k0 + tig][nb];
                b[j][1] = ws[k0 + tig + 4][nb];
            }
#pragma unroll
            for (int i = 0; i < 2; i++)
#pragma unroll
                for (int j = 0; j < 4; j++)
                    mma_tf32(acc[i][j], a[i], b[j]);
        }
        __syncthreads();
    }

#pragma unroll
    for (int i = 0; i < 2; i++) {
        int r_lo = row0 + wm * 32 + i * 16 + g;
        int r_hi = r_lo + 8;
        float d_lo = (r_lo < NN) ? g_dis[r_lo] : 0.f;
        float d_hi = (r_hi < NN) ? g_dis[r_hi] : 0.f;
#pragma unroll
        for (int j = 0; j < 4; j++) {
            int c = wn * 32 + j * 8 + 2 * tig;
            if (r_lo < NN)
                *(float2*)(g_hs1 + (size_t)r_lo * HID + c) =
                    make_float2(d_lo * acc[i][j][0], d_lo * acc[i][j][1]);
            if (r_hi < NN)
                *(float2*)(g_hs1 + (size_t)r_hi * HID + c) =
                    make_float2(d_hi * acc[i][j][2], d_hi * acc[i][j][3]);
        }
    }
}

// ---------------- threefry2x32 (JAX partitionable), key (0, 42) -------------
__device__ __forceinline__ uint32_t rotl32(uint32_t x, int r) {
    return (x << r) | (x >> (32 - r));
}

__device__ __forceinline__ uint32_t tf_bits(uint32_t i) {
    uint32_t x0 = 0u, x1 = i;
    const uint32_t k0 = 0u, k1 = 42u, k2 = 0x1BD11BDAu ^ 42u;
    x0 += k0; x1 += k1;
#define TF_ROUND(r) { x0 += x1; x1 = rotl32(x1, r); x1 ^= x0; }
    TF_ROUND(13) TF_ROUND(15) TF_ROUND(26) TF_ROUND(6)
    x0 += k1; x1 += k2 + 1u;
    TF_ROUND(17) TF_ROUND(29) TF_ROUND(16) TF_ROUND(24)
    x0 += k2; x1 += k0 + 2u;
    TF_ROUND(13) TF_ROUND(15) TF_ROUND(26) TF_ROUND(6)
    x0 += k0; x1 += k1 + 3u;
    TF_ROUND(17) TF_ROUND(29) TF_ROUND(16) TF_ROUND(24)
    x0 += k1; x1 += k2 + 4u;
    TF_ROUND(13) TF_ROUND(15) TF_ROUND(26) TF_ROUND(6)
    x0 += k2; x1 += k0 + 5u;
#undef TF_ROUND
    return x0 ^ x1;
}

// ---------------- agg1: warp/node, lane=(chunk, neighbor-slot) --------------
// 64 floats/row = 16 float4 chunks; 2 neighbor slots; unroll 2 -> 4 rows in flight
__global__ void k_agg1(const float* __restrict__ b1) {
    int node = blockIdx.x * (blockDim.x >> 5) + (threadIdx.x >> 5);
    if (node >= NN) return;
    int lane = threadIdx.x & 31;
    int c4 = lane & 15, p = lane >> 4;
    const float4* hv = (const float4*)g_hs1;

    float4 acc = make_float4(0.f, 0.f, 0.f, 0.f);
    if (p == 0) acc = hv[(size_t)node * 16 + c4];        // self-loop

    int beg = g_offs[node], end = g_offs[node + 1];
    int k = beg + p;
    for (; k + 2 < end; k += 4) {
        int s0 = __ldg(&g_csr[k]);
        int s1 = __ldg(&g_csr[k + 2]);
        float4 v0 = hv[(size_t)s0 * 16 + c4];
        float4 v1 = hv[(size_t)s1 * 16 + c4];
        acc.x += v0.x; acc.y += v0.y; acc.z += v0.z; acc.w += v0.w;
        acc.x += v1.x; acc.y += v1.y; acc.z += v1.z; acc.w += v1.w;
    }
    if (k < end) {
        int s = __ldg(&g_csr[k]);
        float4 v = hv[(size_t)s * 16 + c4];
        acc.x += v.x; acc.y += v.y; acc.z += v.z; acc.w += v.w;
    }

    acc.x += __shfl_down_sync(0xFFFFFFFFu, acc.x, 16);
    acc.y += __shfl_down_sync(0xFFFFFFFFu, acc.y, 16);
    acc.z += __shfl_down_sync(0xFFFFFFFFu, acc.z, 16);
    acc.w += __shfl_down_sync(0xFFFFFFFFu, acc.w, 16);

    if (p == 0) {
        float d = g_dis[node];
        float4 bb = ((const float4*)b1)[c4];
        float4 v;
        v.x = fmaxf(fmaf(d, acc.x, bb.x), 0.f);
        v.y = fmaxf(fmaf(d, acc.y, bb.y), 0.f);
        v.z = fmaxf(fmaf(d, acc.z, bb.z), 0.f);
        v.w = fmaxf(fmaf(d, acc.w, bb.w), 0.f);
        uint32_t i0 = (uint32_t)node * HID + c4 * 4;
        v.x = (tf_bits(i0)     < 0x80000000u) ? v.x * 2.0f : 0.f;
        v.y = (tf_bits(i0 + 1) < 0x80000000u) ? v.y * 2.0f : 0.f;
        v.z = (tf_bits(i0 + 2) < 0x80000000u) ? v.z * 2.0f : 0.f;
        v.w = (tf_bits(i0 + 3) < 0x80000000u) ? v.w * 2.0f : 0.f;
        ((float4*)g_h)[(size_t)node * 16 + c4] = v;
    }
}

// ---------------- GEMM2: hs2 = dis .* (h @ W2) ------------------------------
__global__ void k_gemm2(const float* __restrict__ W2) {
    __shared__ float hsm[64][65];
    __shared__ float w2s[64][OUTD];
    const int row0 = blockIdx.x * 64;
    const int t = threadIdx.x;

    for (int idx = t; idx < 64 * 64; idx += 320) {
        int r = idx >> 6, k = idx & 63;
        int gr = row0 + r;
        hsm[r][k] = (gr < NN) ? g_h[(size_t)gr * HID + k] : 0.f;
    }
    for (int idx = t; idx < 64 * OUTD; idx += 320)
        w2s[idx / OUTD][idx % OUTD] = W2[idx];
    __syncthreads();

    int r8 = t / OUTD;
    int c = t % OUTD;
    float acc[8] = {};
#pragma unroll
    for (int k = 0; k < 64; k++) {
        float b = w2s[k][c];
#pragma unroll
        for (int i = 0; i < 8; i++)
            acc[i] = fmaf(hsm[r8 * 8 + i][k], b, acc[i]);
    }
#pragma unroll
    for (int i = 0; i < 8; i++) {
        int row = row0 + r8 * 8 + i;
        if (row < NN)
            g_hs2[(size_t)row * OUTD + c] = g_dis[row] * acc[i];
    }
}

// ---------------- agg2: warp/node, 10 float4 chunks x 3 neighbor slots ------
__global__ void k_agg2(const float* __restrict__ b2, float* __restrict__ out) {
    int node = blockIdx.x * (blockDim.x >> 5) + (threadIdx.x >> 5);
    if (node >= NN) return;
    int lane = threadIdx.x & 31;
    int c = lane % 10;
    int p = (lane < 30) ? (lane / 10) : 3;     // slots 0..2; lanes 30,31 idle
    const float4* hv = (const float4*)g_hs2;   // row stride 10 float4

    float4 acc = make_float4(0.f, 0.f, 0.f, 0.f);
    if (lane < 10) acc = hv[(size_t)node * 10 + c];   // self-loop

    int beg = g_offs[node], end = g_offs[node + 1];
    if (p < 3) {
        int k = beg + p;
        for (; k + 3 < end; k += 6) {
            int s0 = __ldg(&g_csr[k]);
            int s1 = __ldg(&g_csr[k + 3]);
            float4 v0 = hv[(size_t)s0 * 10 + c];
            float4 v1 = hv[(size_t)s1 * 10 + c];
            acc.x += v0.x; acc.y += v0.y; acc.z += v0.z; acc.w += v0.w;
            acc.x += v1.x; acc.y += v1.y; acc.z += v1.z; acc.w += v1.w;
        }
        if (k < end) {
            int s = __ldg(&g_csr[k]);
            float4 v = hv[(size_t)s * 10 + c];
            acc.x += v.x; acc.y += v.y; acc.z += v.z; acc.w += v.w;
        }
    }

    // combine 3 slots: lanes 30/31 contribute 0
    float rx = acc.x + __shfl_down_sync(0xFFFFFFFFu, acc.x, 10) + __shfl_down_sync(0xFFFFFFFFu, acc.x, 20);
    float ry = acc.y + __shfl_down_sync(0xFFFFFFFFu, acc.y, 10) + __shfl_down_sync(0xFFFFFFFFu, acc.y, 20);
    float rz = acc.z + __shfl_down_sync(0xFFFFFFFFu, acc.z, 10) + __shfl_down_sync(0xFFFFFFFFu, acc.z, 20);
    float rw = acc.w + __shfl_down_sync(0xFFFFFFFFu, acc.w, 10) + __shfl_down_sync(0xFFFFFFFFu, acc.w, 20);

    float4 v = make_float4(-CUDART_INF_F, -CUDART_INF_F, -CUDART_INF_F, -CUDART_INF_F);
    if (lane < 10) {
        float d = g_dis[node];
        float4 bb = ((const float4*)b2)[c];
        v.x = fmaf(d, rx, bb.x);
        v.y = fmaf(d, ry, bb.y);
        v.z = fmaf(d, rz, bb.z);
        v.w = fmaf(d, rw, bb.w);
    }
    float m = fmaxf(fmaxf(v.x, v.y), fmaxf(v.z, v.w));
#pragma unroll
    for (int o = 16; o; o >>= 1) m = fmaxf(m, __shfl_xor_sync(0xFFFFFFFFu, m, o));
    float s = 0.f;
    if (lane < 10)
        s = expf(v.x - m) + expf(v.y - m) + expf(v.z - m) + expf(v.w - m);
#pragma unroll
    for (int o = 16; o; o >>= 1) s += __shfl_xor_sync(0xFFFFFFFFu, s, o);
    float lse = m + logf(s);

    if (lane < 10) {
        float4 o4 = make_float4(v.x - lse, v.y - lse, v.z - lse, v.w - lse);
        ((float4*)out)[(size_t)node * 10 + c] = o4;
    }
}

// ---------------- launch -----------------------------------------------------
extern "C" void kernel_launch(void* const* d_in, const int* in_sizes, int n_in,
                              void* d_out, int out_size) {
    const float* x  = (const float*)d_in[0];
    const int*   ei = (const int*)d_in[1];     // [2, NE] row-major
    const float* W1 = (const float*)d_in[2];
    const float* b1 = (const float*)d_in[3];
    const float* W2 = (const float*)d_in[4];
    const float* b2 = (const float*)d_in[5];
    float* out = (float*)d_out;
    const int* src = ei;
    const int* dst = ei + NE;

    const int NB = (NN + 1023) / 1024;   // 49

    k_zero<<<(NN + 255) / 256, 256>>>();
    k_count<<<(NE / 4 + 255) / 256, 256>>>(dst);
    k_scan1<<<NB, 1024>>>();
    k_scan2<<<1, 64>>>();
    k_scan3<<<NB, 1024>>>();
    k_fill<<<(NE / 4 + 255) / 256, 256>>>(src, dst);

    k_gemm1<<<(NN + 127) / 128, 256>>>(x, W1);
    k_agg1<<<(NN * 32 + 255) / 256, 256>>>(b1);

    k_gemm2<<<(NN + 63) / 64, 320>>>(W2);
    k_agg2<<<(NN * 32 + 255) / 256, 256>>>(b2, out);
}